// round 1
// baseline (speedup 1.0000x reference)
#include <cuda_runtime.h>

// SAGAN self-attention, B=8, C=64, H=W=64 (N=4096), Ck=C/8=8.
// out = gamma * (h @ softmax_n(f^T g)) + x
// Implemented as streaming (flash-style) attention over n with online softmax.

#define Bb 8
#define Cc 64
#define Nn 4096
#define CK 8
#define ROWS 80     // 8 f-rows + 8 g-rows + 64 h-rows
#define MT 64       // query columns per block
#define NT 64       // key tile

// Scratch for projections (allocation-free rule: __device__ globals)
__device__ float d_fbuf[Bb * CK * Nn];
__device__ float d_gbuf[Bb * CK * Nn];
__device__ float d_hbuf[Bb * Cc * Nn];

// ---------------------------------------------------------------------------
// Kernel 1: fused projections f = wq x, g = wk x, h = wv x
// grid (N/256, B), 256 threads; thread owns one pixel n, streams 80 rows.
// ---------------------------------------------------------------------------
__global__ __launch_bounds__(256) void proj_kernel(
    const float* __restrict__ x,
    const float* __restrict__ wq,
    const float* __restrict__ wk,
    const float* __restrict__ wv)
{
    __shared__ float w_s[ROWS * Cc];
    const int b   = blockIdx.y;
    const int n0  = blockIdx.x * 256;
    const int tid = threadIdx.x;

    for (int e = tid; e < ROWS * Cc; e += 256) {
        int r = e >> 6, c = e & 63;
        float v;
        if (r < 8)       v = wq[r * Cc + c];
        else if (r < 16) v = wk[(r - 8) * Cc + c];
        else             v = wv[(r - 16) * Cc + c];
        w_s[e] = v;
    }
    __syncthreads();

    const int n = n0 + tid;
    float xr[Cc];
#pragma unroll
    for (int c = 0; c < Cc; c++) xr[c] = x[(b * Cc + c) * Nn + n];

    for (int r = 0; r < ROWS; r++) {
        const float4* wr = (const float4*)&w_s[r * Cc];
        float acc = 0.f;
#pragma unroll
        for (int q = 0; q < Cc / 4; q++) {
            float4 w4 = wr[q];
            acc += w4.x * xr[4 * q + 0];
            acc += w4.y * xr[4 * q + 1];
            acc += w4.z * xr[4 * q + 2];
            acc += w4.w * xr[4 * q + 3];
        }
        if (r < 8)       d_fbuf[(b * CK + r) * Nn + n] = acc;
        else if (r < 16) d_gbuf[(b * CK + (r - 8)) * Nn + n] = acc;
        else             d_hbuf[(b * Cc + (r - 16)) * Nn + n] = acc;
    }
}

// ---------------------------------------------------------------------------
// Kernel 2: streaming attention with online softmax over n.
// grid (N/MT, B), 256 threads. Thread = (m = tid&63, channel group cg = tid>>6,
// 16 channels each). Online stats runM/runL per column m live in smem.
// ---------------------------------------------------------------------------
__global__ __launch_bounds__(256) void attn_kernel(
    const float* __restrict__ x,
    const float* __restrict__ gamma,
    float* __restrict__ out)
{
    __shared__ float f_s[CK][NT];        // keys tile   [k][n]
    __shared__ float h_s[NT][Cc];        // values tile [n][c] (transposed for f4 LDS)
    __shared__ float s_s[NT * 65];       // scores, padded stride 65 (conflict-free cols)
    __shared__ float runM[MT], runL[MT], scaleS[MT];
    __shared__ float partred[4 * MT];

    const int b   = blockIdx.y;
    const int m0  = blockIdx.x * MT;
    const int tid = threadIdx.x;
    const int m   = tid & 63;
    const int cg  = tid >> 6;      // 0..3
    const int cb  = cg * 16;       // channel base

    float g_reg[CK];
#pragma unroll
    for (int k = 0; k < CK; k++)
        g_reg[k] = d_gbuf[(b * CK + k) * Nn + m0 + m];

    float o[16];
#pragma unroll
    for (int j = 0; j < 16; j++) o[j] = 0.f;

    if (tid < MT) { runM[tid] = -1e30f; runL[tid] = 0.f; }

    for (int nt = 0; nt < Nn / NT; nt++) {
        const int n0 = nt * NT;
        __syncthreads();   // guard smem reuse from previous tile

        // --- load f tile: 8x64 ---
        for (int e = tid; e < CK * NT; e += 256) {
            int k = e >> 6, nn = e & 63;
            f_s[k][nn] = d_fbuf[(b * CK + k) * Nn + n0 + nn];
        }
        // --- load h tile transposed: thread owns (c = tid>>2, 16 n's) ---
        {
            const int c  = tid >> 2;
            const int nb = (tid & 3) * 16;
            const float4* hp = (const float4*)&d_hbuf[(b * Cc + c) * Nn + n0 + nb];
#pragma unroll
            for (int q = 0; q < 4; q++) {
                float4 v = hp[q];
                h_s[nb + 4 * q + 0][c] = v.x;
                h_s[nb + 4 * q + 1][c] = v.y;
                h_s[nb + 4 * q + 2][c] = v.z;
                h_s[nb + 4 * q + 3][c] = v.w;
            }
        }
        __syncthreads();

        // --- scores: thread computes s[nn][m] for nn in [cg*16, cg*16+16) ---
        float lmax = -1e30f;
#pragma unroll
        for (int t = 0; t < 16; t++) {
            int nn = cg * 16 + t;
            float acc = 0.f;
#pragma unroll
            for (int k = 0; k < CK; k++) acc += f_s[k][nn] * g_reg[k];
            s_s[nn * 65 + m] = acc;
            lmax = fmaxf(lmax, acc);
        }
        partred[cg * MT + m] = lmax;
        __syncthreads();

        // --- running max update (one thread per column) ---
        if (tid < MT) {
            float om = runM[tid];
            float tm = fmaxf(fmaxf(partred[tid], partred[MT + tid]),
                             fmaxf(partred[2 * MT + tid], partred[3 * MT + tid]));
            float nm2 = fmaxf(om, tm);
            scaleS[tid] = __expf(om - nm2);
            runM[tid]   = nm2;
        }
        __syncthreads();

        // --- exponentiate, partial sums, rescale accumulators ---
        const float nm = runM[m];
        float psum = 0.f;
#pragma unroll
        for (int t = 0; t < 16; t++) {
            int idx = (cg * 16 + t) * 65 + m;
            float p = __expf(s_s[idx] - nm);
            s_s[idx] = p;
            psum += p;
        }
        partred[cg * MT + m] = psum;
        const float sc = scaleS[m];
#pragma unroll
        for (int j = 0; j < 16; j++) o[j] *= sc;
        __syncthreads();

        if (tid < MT)
            runL[tid] = runL[tid] * scaleS[tid]
                      + partred[tid] + partred[MT + tid]
                      + partred[2 * MT + tid] + partred[3 * MT + tid];

        // --- PV: o[c,m] += sum_n p[n,m] * h[c,n] ---
#pragma unroll 4
        for (int n = 0; n < NT; n++) {
            float p = s_s[n * 65 + m];
            const float4* hv = (const float4*)&h_s[n][cb];
            float4 h0 = hv[0], h1 = hv[1], h2 = hv[2], h3 = hv[3];
            o[0]  += p * h0.x;  o[1]  += p * h0.y;  o[2]  += p * h0.z;  o[3]  += p * h0.w;
            o[4]  += p * h1.x;  o[5]  += p * h1.y;  o[6]  += p * h1.z;  o[7]  += p * h1.w;
            o[8]  += p * h2.x;  o[9]  += p * h2.y;  o[10] += p * h2.z;  o[11] += p * h2.w;
            o[12] += p * h3.x;  o[13] += p * h3.y;  o[14] += p * h3.z;  o[15] += p * h3.w;
        }
    }
    __syncthreads();   // runL final values visible

    const float invL = 1.0f / runL[m];
    const float ga   = gamma[0];
#pragma unroll
    for (int j = 0; j < 16; j++) {
        int c  = cb + j;
        int gi = (b * Cc + c) * Nn + m0 + m;
        out[gi] = ga * (o[j] * invL) + x[gi];
    }
}

// ---------------------------------------------------------------------------
extern "C" void kernel_launch(void* const* d_in, const int* in_sizes, int n_in,
                              void* d_out, int out_size)
{
    const float* x     = (const float*)d_in[0];
    const float* wq    = (const float*)d_in[1];
    const float* wk    = (const float*)d_in[2];
    const float* wv    = (const float*)d_in[3];
    const float* gamma = (const float*)d_in[4];
    float* out = (float*)d_out;

    (void)in_sizes; (void)n_in; (void)out_size;

    proj_kernel<<<dim3(Nn / 256, Bb), 256>>>(x, wq, wk, wv);
    attn_kernel<<<dim3(Nn / MT, Bb), 256>>>(x, gamma, out);
}

// round 3
// speedup vs baseline: 4.8327x; 4.8327x over previous
#include <cuda_runtime.h>
#include <cstdint>

// SAGAN self-attention, B=8, C=64, N=4096, Ck=8.
// out = gamma * (h @ softmax_n(f^T g)) + x
// Flash-style streaming over n; warp-level tf32 mma.sync (sm_103 baseline PTX,
// no tcgen05 — the harness PTX-targets compute_103 which rejects 'a' features).
// Softmax without max-subtraction: scores ~ N(0,8); |s|*log2e <= ~25, exp2
// cannot overflow fp32. log2e folded into the g projection.

#define Bb 8
#define Cc 64
#define Nn 4096
#define CK 8
#define MT 128      // m per block
#define NT 64       // n tile
#define NITER (Nn / NT)
#define LOG2E 1.44269504088896340736f

// Projection scratch (allocation-free rule: __device__ globals). All tf32-rounded.
__device__ float d_fbuf[Bb * CK * Nn];   // [b][k][n]   (n contiguous)
__device__ float d_gbuf[Bb * Nn * CK];   // [b][m][k]   (k contiguous, * log2e)
__device__ float d_hbuf[Bb * Nn * Cc];   // [b][n][c]   (c contiguous)

// ---------------- helpers ----------------
__device__ __forceinline__ uint32_t smem_u32(const void* p) {
    uint32_t a;
    asm("{ .reg .u64 t; cvta.to.shared.u64 t, %1; cvt.u32.u64 %0, t; }" : "=r"(a) : "l"(p));
    return a;
}
__device__ __forceinline__ float f2tf(float x) {
    uint32_t r;
    asm("cvt.rna.tf32.f32 %0, %1;" : "=r"(r) : "f"(x));
    return __uint_as_float(r);
}
__device__ __forceinline__ uint32_t f2tfb(float x) {
    uint32_t r;
    asm("cvt.rna.tf32.f32 %0, %1;" : "=r"(r) : "f"(x));
    return r;
}
__device__ __forceinline__ float ex2(float x) {
    float r;
    asm("ex2.approx.f32 %0, %1;" : "=f"(r) : "f"(x));
    return r;
}

#define MMA_TF32(d, a0, a1, a2, a3, b0, b1)                                   \
    asm volatile("mma.sync.aligned.m16n8k8.row.col.f32.tf32.tf32.f32 "        \
                 "{%0,%1,%2,%3}, {%4,%5,%6,%7}, {%8,%9}, {%0,%1,%2,%3};"      \
                 : "+f"((d)[0]), "+f"((d)[1]), "+f"((d)[2]), "+f"((d)[3])     \
                 : "r"(a0), "r"(a1), "r"(a2), "r"(a3), "r"(b0), "r"(b1))

#define CP16(dst, src) \
    asm volatile("cp.async.cg.shared.global [%0], [%1], 16;" :: "r"(dst), "l"(src))
#define CP_COMMIT() asm volatile("cp.async.commit_group;" ::: "memory")
#define CP_WAIT1()  asm volatile("cp.async.wait_group 1;" ::: "memory")

// ---------------------------------------------------------------------------
// Kernel 1: fused projections.
//   f = wq x  -> d_fbuf [b][k][n]        (tf32)
//   g = wk x * log2e -> d_gbuf [b][m][k] (tf32)
//   h = wv x  -> d_hbuf [b][n][c]        (tf32, coalesced via smem transpose)
// ---------------------------------------------------------------------------
__global__ __launch_bounds__(128) void proj_kernel(
    const float* __restrict__ x,
    const float* __restrict__ wq,
    const float* __restrict__ wk,
    const float* __restrict__ wv)
{
    __shared__ float w_s[80 * Cc];
    __shared__ float h_sm[128][17];
    const int b   = blockIdx.y;
    const int n0  = blockIdx.x * 128;
    const int tid = threadIdx.x;

    for (int e = tid; e < 80 * Cc; e += 128) {
        int r = e >> 6, c = e & 63;
        float v;
        if (r < 8)       v = wq[r * Cc + c];
        else if (r < 16) v = wk[(r - 8) * Cc + c];
        else             v = wv[(r - 16) * Cc + c];
        w_s[e] = v;
    }
    __syncthreads();

    const int n = n0 + tid;
    float xr[Cc];
#pragma unroll
    for (int c = 0; c < Cc; c++) xr[c] = x[(b * Cc + c) * Nn + n];

    // f and g rows (0..15)
    float ga[8];
#pragma unroll
    for (int r = 0; r < 16; r++) {
        const float4* wr = (const float4*)&w_s[r * Cc];
        float acc = 0.f;
#pragma unroll
        for (int q = 0; q < Cc / 4; q++) {
            float4 w4 = wr[q];
            acc += w4.x * xr[4 * q + 0];
            acc += w4.y * xr[4 * q + 1];
            acc += w4.z * xr[4 * q + 2];
            acc += w4.w * xr[4 * q + 3];
        }
        if (r < 8) d_fbuf[(b * CK + r) * Nn + n] = f2tf(acc);
        else       ga[r - 8] = f2tf(acc * LOG2E);
    }
    {
        float4* gp = (float4*)(d_gbuf + (size_t)(b * Nn + n) * CK);
        gp[0] = make_float4(ga[0], ga[1], ga[2], ga[3]);
        gp[1] = make_float4(ga[4], ga[5], ga[6], ga[7]);
    }

    // h rows in 4 chunks of 16 c, transposed through smem for coalesced stores
    for (int chunk = 0; chunk < 4; chunk++) {
#pragma unroll
        for (int cc = 0; cc < 16; cc++) {
            int r = 16 + chunk * 16 + cc;
            const float4* wr = (const float4*)&w_s[r * Cc];
            float acc = 0.f;
#pragma unroll
            for (int q = 0; q < Cc / 4; q++) {
                float4 w4 = wr[q];
                acc += w4.x * xr[4 * q + 0];
                acc += w4.y * xr[4 * q + 1];
                acc += w4.z * xr[4 * q + 2];
                acc += w4.w * xr[4 * q + 3];
            }
            h_sm[tid][cc] = f2tf(acc);
        }
        __syncthreads();
        for (int e = tid; e < 128 * 16; e += 128) {
            int nl = e >> 4, cc = e & 15;
            d_hbuf[(size_t)(b * Nn + n0 + nl) * Cc + chunk * 16 + cc] = h_sm[nl][cc];
        }
        __syncthreads();
    }
}

// ---------------------------------------------------------------------------
// Kernel 2: warp-mma tf32 flash attention.
//   Block: 128 m x 64 c, 4 warps (warp = 32 m = 2 m-frags of m16).
//   Per n-tile (64): S = g f^T (one K=8 mma per 16x8 tile) -> exp2 ->
//   in-register C->A fragment conversion (shfl) -> O += P h^T (K=64).
// ---------------------------------------------------------------------------
__global__ __launch_bounds__(128) void attn_mma_kernel(
    const float* __restrict__ x,
    const float* __restrict__ gamma,
    float* __restrict__ out)
{
    __shared__ float fs[2][CK][72];   // f tile  [k][n], stride 72 (==8 mod 32)
    __shared__ float hs[2][NT][72];   // h tile  [n][c], stride 72

    const int tid  = threadIdx.x;
    const int w    = tid >> 5;
    const int lane = tid & 31;
    const int g    = lane >> 2;        // row-in-group 0..7
    const int tg   = lane & 3;         // thread-in-group 0..3
    const int b    = blockIdx.y;
    const int m0   = blockIdx.x * MT;

    const uint32_t fsb = smem_u32(&fs[0][0][0]);
    const uint32_t hsb = smem_u32(&hs[0][0][0]);

    // ---- g fragments (held in registers for the whole kernel) ----
    uint32_t gfr[2][4];
#pragma unroll
    for (int mf = 0; mf < 2; mf++) {
        const int mb = m0 + w * 32 + mf * 16;
        const float* gp = d_gbuf + (size_t)(b * Nn) * CK;
        gfr[mf][0] = __float_as_uint(gp[(mb + g) * CK + tg]);
        gfr[mf][1] = __float_as_uint(gp[(mb + 8 + g) * CK + tg]);
        gfr[mf][2] = __float_as_uint(gp[(mb + g) * CK + tg + 4]);
        gfr[mf][3] = __float_as_uint(gp[(mb + 8 + g) * CK + tg + 4]);
    }

    float O[2][8][4];
#pragma unroll
    for (int mf = 0; mf < 2; mf++)
#pragma unroll
        for (int cf = 0; cf < 8; cf++)
#pragma unroll
            for (int j = 0; j < 4; j++) O[mf][cf][j] = 0.f;
    float Ls[2][2] = {{0.f, 0.f}, {0.f, 0.f}};

    // ---- cp.async tile loader ----
    auto issue_tile = [&](int it) {
        const int p  = it & 1;
        const int n0 = it * NT;
        if (tid < 128) {  // f: 8 rows x 16 chunks
            int row = tid >> 4, ch = tid & 15;
            CP16(fsb + (uint32_t)(p * (CK * 72 * 4) + row * 288 + ch * 16),
                 d_fbuf + (size_t)(b * CK + row) * Nn + n0 + ch * 4);
        }
#pragma unroll
        for (int t = 0; t < 8; t++) {  // h: 64 rows x 16 chunks
            int e = tid + t * 128;
            int row = e >> 4, ch = e & 15;
            CP16(hsb + (uint32_t)(p * (NT * 72 * 4) + row * 288 + ch * 16),
                 d_hbuf + (size_t)(b * Nn + n0 + row) * Cc + ch * 4);
        }
    };

    issue_tile(0); CP_COMMIT();
    issue_tile(1); CP_COMMIT();

    const int src1 = (lane & ~3) | (tg >> 1);
    const int src2 = src1 + 2;
    const int rsel = tg & 1;

    for (int it = 0; it < NITER; ++it) {
        const int p = it & 1;
        CP_WAIT1();
        __syncthreads();

#pragma unroll
        for (int nf = 0; nf < 8; nf++) {
            // GEMM1 B fragment from f tile
            uint32_t fb0 = __float_as_uint(fs[p][tg][nf * 8 + g]);
            uint32_t fb1 = __float_as_uint(fs[p][tg + 4][nf * 8 + g]);

            float c0[4] = {0.f, 0.f, 0.f, 0.f};
            float c1[4] = {0.f, 0.f, 0.f, 0.f};
            MMA_TF32(c0, gfr[0][0], gfr[0][1], gfr[0][2], gfr[0][3], fb0, fb1);
            MMA_TF32(c1, gfr[1][0], gfr[1][1], gfr[1][2], gfr[1][3], fb0, fb1);

            // exp2, row-sum, C->A fragment conversion
            uint32_t pa[2][4];
#pragma unroll
            for (int mf = 0; mf < 2; mf++) {
                float* c = mf ? c1 : c0;
                float e0 = ex2(c[0]), e1 = ex2(c[1]), e2 = ex2(c[2]), e3 = ex2(c[3]);
                Ls[mf][0] += e0 + e1;
                Ls[mf][1] += e2 + e3;
                float t0, t1;
                t0 = __shfl_sync(0xffffffffu, e0, src1);
                t1 = __shfl_sync(0xffffffffu, e1, src1);
                pa[mf][0] = f2tfb(rsel ? t1 : t0);
                t0 = __shfl_sync(0xffffffffu, e2, src1);
                t1 = __shfl_sync(0xffffffffu, e3, src1);
                pa[mf][1] = f2tfb(rsel ? t1 : t0);
                t0 = __shfl_sync(0xffffffffu, e0, src2);
                t1 = __shfl_sync(0xffffffffu, e1, src2);
                pa[mf][2] = f2tfb(rsel ? t1 : t0);
                t0 = __shfl_sync(0xffffffffu, e2, src2);
                t1 = __shfl_sync(0xffffffffu, e3, src2);
                pa[mf][3] = f2tfb(rsel ? t1 : t0);
            }

            // GEMM2: O[mf][cf] += P(16x8 slice) * h^T
#pragma unroll
            for (int cf = 0; cf < 8; cf++) {
                uint32_t hb0 = __float_as_uint(hs[p][nf * 8 + tg][cf * 8 + g]);
                uint32_t hb1 = __float_as_uint(hs[p][nf * 8 + tg + 4][cf * 8 + g]);
                MMA_TF32(O[0][cf], pa[0][0], pa[0][1], pa[0][2], pa[0][3], hb0, hb1);
                MMA_TF32(O[1][cf], pa[1][0], pa[1][1], pa[1][2], pa[1][3], hb0, hb1);
            }
        }
        __syncthreads();
        if (it + 2 < NITER) issue_tile(it + 2);
        CP_COMMIT();
    }

    // ---- reduce row sums across the 4-lane groups ----
#pragma unroll
    for (int mf = 0; mf < 2; mf++)
#pragma unroll
        for (int h = 0; h < 2; h++) {
            float v = Ls[mf][h];
            v += __shfl_xor_sync(0xffffffffu, v, 1);
            v += __shfl_xor_sync(0xffffffffu, v, 2);
            Ls[mf][h] = v;
        }

    // ---- epilogue: out = gamma * O / L + x ----
    const float ga = gamma[0];
#pragma unroll
    for (int mf = 0; mf < 2; mf++) {
        const int r0 = m0 + w * 32 + mf * 16 + g;
        const float s0 = ga / Ls[mf][0];
        const float s1 = ga / Ls[mf][1];
#pragma unroll
        for (int cf = 0; cf < 8; cf++) {
            const int c0i = cf * 8 + 2 * tg;
            int i00 = (b * Cc + c0i) * Nn + r0;
            int i01 = (b * Cc + c0i + 1) * Nn + r0;
            int i10 = (b * Cc + c0i) * Nn + r0 + 8;
            int i11 = (b * Cc + c0i + 1) * Nn + r0 + 8;
            out[i00] = fmaf(s0, O[mf][cf][0], x[i00]);
            out[i01] = fmaf(s0, O[mf][cf][1], x[i01]);
            out[i10] = fmaf(s1, O[mf][cf][2], x[i10]);
            out[i11] = fmaf(s1, O[mf][cf][3], x[i11]);
        }
    }
}

// ---------------------------------------------------------------------------
extern "C" void kernel_launch(void* const* d_in, const int* in_sizes, int n_in,
                              void* d_out, int out_size)
{
    const float* x     = (const float*)d_in[0];
    const float* wq    = (const float*)d_in[1];
    const float* wk    = (const float*)d_in[2];
    const float* wv    = (const float*)d_in[3];
    const float* gamma = (const float*)d_in[4];
    float* out = (float*)d_out;
    (void)in_sizes; (void)n_in; (void)out_size;

    proj_kernel<<<dim3(Nn / 128, Bb), 128>>>(x, wq, wk, wv);
    attn_mma_kernel<<<dim3(Nn / MT, Bb), 128>>>(x, gamma, out);
}

// round 4
// speedup vs baseline: 8.8067x; 1.8223x over previous
#include <cuda_runtime.h>
#include <cstdint>

// SAGAN self-attention, B=8, C=64, N=4096, Ck=8.
// out = gamma * (h @ softmax_n(f^T g)) + x
// Flash streaming over n; gemm1 = tf32 m16n8k8, gemm2 = bf16 m16n8k16 with the
// C->A fragment pack trick (no shfl). Softmax without max-subtraction
// (|s|*log2e <= ~25, exp2 cannot overflow fp32); log2e folded into g.

#define Bb 8
#define Cc 64
#define Nn 4096
#define CK 8
#define MT 128      // m per block
#define NT 128      // n tile
#define NITER (Nn / NT)
#define LOG2E 1.44269504088896340736f

// Projection scratch (allocation-free rule: __device__ globals).
__device__ float    d_fbuf[Bb * CK * Nn];        // [b][k][n]  tf32, n contiguous
__device__ float    d_gbuf[Bb * Nn * CK];        // [b][m][k]  tf32 * log2e
__device__ uint32_t d_hpak[Bb * (Nn / 2) * Cc];  // [b][npair][c] bf16x2 (n even lo, odd hi)

// ---------------- helpers ----------------
__device__ __forceinline__ uint32_t smem_u32(const void* p) {
    uint32_t a;
    asm("{ .reg .u64 t; cvta.to.shared.u64 t, %1; cvt.u32.u64 %0, t; }" : "=r"(a) : "l"(p));
    return a;
}
__device__ __forceinline__ float f2tf(float x) {
    uint32_t r;
    asm("cvt.rna.tf32.f32 %0, %1;" : "=r"(r) : "f"(x));
    return __uint_as_float(r);
}
__device__ __forceinline__ float ex2(float x) {
    float r;
    asm("ex2.approx.f32 %0, %1;" : "=f"(r) : "f"(x));
    return r;
}
__device__ __forceinline__ uint32_t packbf(float lo, float hi) {
    uint32_t d;
    asm("cvt.rn.bf16x2.f32 %0, %1, %2;" : "=r"(d) : "f"(hi), "f"(lo));
    return d;
}

#define MMA_TF32(d, a0, a1, a2, a3, b0, b1)                                   \
    asm volatile("mma.sync.aligned.m16n8k8.row.col.f32.tf32.tf32.f32 "        \
                 "{%0,%1,%2,%3}, {%4,%5,%6,%7}, {%8,%9}, {%0,%1,%2,%3};"      \
                 : "+f"((d)[0]), "+f"((d)[1]), "+f"((d)[2]), "+f"((d)[3])     \
                 : "r"(a0), "r"(a1), "r"(a2), "r"(a3), "r"(b0), "r"(b1))

#define MMA_BF16(d, a0, a1, a2, a3, b0, b1)                                   \
    asm volatile("mma.sync.aligned.m16n8k16.row.col.f32.bf16.bf16.f32 "       \
                 "{%0,%1,%2,%3}, {%4,%5,%6,%7}, {%8,%9}, {%0,%1,%2,%3};"      \
                 : "+f"((d)[0]), "+f"((d)[1]), "+f"((d)[2]), "+f"((d)[3])     \
                 : "r"(a0), "r"(a1), "r"(a2), "r"(a3), "r"(b0), "r"(b1))

#define CP16(dst, src) \
    asm volatile("cp.async.cg.shared.global [%0], [%1], 16;" :: "r"(dst), "l"(src))
#define CP_COMMIT() asm volatile("cp.async.commit_group;" ::: "memory")
#define CP_WAIT1()  asm volatile("cp.async.wait_group 1;" ::: "memory")

// ---------------------------------------------------------------------------
// Kernel 1: fused projections.
//   f = wq x            -> d_fbuf [b][k][n]        (tf32)
//   g = wk x * log2e    -> d_gbuf [b][m][k]        (tf32)
//   h = wv x            -> d_hpak [b][n/2][c]      (bf16x2 pairs along n)
// ---------------------------------------------------------------------------
__global__ __launch_bounds__(128) void proj_kernel(
    const float* __restrict__ x,
    const float* __restrict__ wq,
    const float* __restrict__ wk,
    const float* __restrict__ wv)
{
    __shared__ float w_s[80 * Cc];
    __shared__ float h_sm[128][17];
    const int b   = blockIdx.y;
    const int n0  = blockIdx.x * 128;
    const int tid = threadIdx.x;

    for (int e = tid; e < 80 * Cc; e += 128) {
        int r = e >> 6, c = e & 63;
        float v;
        if (r < 8)       v = wq[r * Cc + c];
        else if (r < 16) v = wk[(r - 8) * Cc + c];
        else             v = wv[(r - 16) * Cc + c];
        w_s[e] = v;
    }
    __syncthreads();

    const int n = n0 + tid;
    float xr[Cc];
#pragma unroll
    for (int c = 0; c < Cc; c++) xr[c] = x[(b * Cc + c) * Nn + n];

    float ga[8];
#pragma unroll
    for (int r = 0; r < 16; r++) {
        const float4* wr = (const float4*)&w_s[r * Cc];
        float acc = 0.f;
#pragma unroll
        for (int q = 0; q < Cc / 4; q++) {
            float4 w4 = wr[q];
            acc += w4.x * xr[4 * q + 0];
            acc += w4.y * xr[4 * q + 1];
            acc += w4.z * xr[4 * q + 2];
            acc += w4.w * xr[4 * q + 3];
        }
        if (r < 8) d_fbuf[(b * CK + r) * Nn + n] = f2tf(acc);
        else       ga[r - 8] = f2tf(acc * LOG2E);
    }
    {
        float4* gp = (float4*)(d_gbuf + (size_t)(b * Nn + n) * CK);
        gp[0] = make_float4(ga[0], ga[1], ga[2], ga[3]);
        gp[1] = make_float4(ga[4], ga[5], ga[6], ga[7]);
    }

    // h rows in 4 chunks of 16 c, transposed through smem, packed bf16x2 pairs
    for (int chunk = 0; chunk < 4; chunk++) {
#pragma unroll
        for (int cc = 0; cc < 16; cc++) {
            int r = 16 + chunk * 16 + cc;
            const float4* wr = (const float4*)&w_s[r * Cc];
            float acc = 0.f;
#pragma unroll
            for (int q = 0; q < Cc / 4; q++) {
                float4 w4 = wr[q];
                acc += w4.x * xr[4 * q + 0];
                acc += w4.y * xr[4 * q + 1];
                acc += w4.z * xr[4 * q + 2];
                acc += w4.w * xr[4 * q + 3];
            }
            h_sm[tid][cc] = acc;
        }
        __syncthreads();
        for (int e = tid; e < 64 * 16; e += 128) {
            int np = e >> 4, cc = e & 15;
            uint32_t v = packbf(h_sm[2 * np][cc], h_sm[2 * np + 1][cc]);
            d_hpak[(size_t)(b * (Nn / 2) + (n0 >> 1) + np) * Cc + chunk * 16 + cc] = v;
        }
        __syncthreads();
    }
}

// ---------------------------------------------------------------------------
// Kernel 2: warp-mma flash attention.
//   Block: 256 threads (8 warps), warp = 16 m rows, MT=128. n-tiles of 128.
//   Per 16-n group: 2 tf32 MMA (S) -> ex2 -> bf16x2 pack (C->A layout match)
//   -> 8 bf16 k16 MMA (O += P h^T). No shfl, P never in smem.
// ---------------------------------------------------------------------------
__global__ __launch_bounds__(256) void attn_mma_kernel(
    const float* __restrict__ x,
    const float* __restrict__ gamma,
    float* __restrict__ out)
{
    __shared__ float    fs[2][CK][136];   // f tile [k][n], stride 136 (==8 mod 32)
    __shared__ uint32_t hs[2][NT / 2][72];// h tile [npair][c] bf16x2, stride 72

    const int tid  = threadIdx.x;
    const int w    = tid >> 5;
    const int lane = tid & 31;
    const int g    = lane >> 2;        // 0..7
    const int tg   = lane & 3;         // 0..3
    const int b    = blockIdx.y;
    const int m0   = blockIdx.x * MT;

    const uint32_t fsb = smem_u32(&fs[0][0][0]);
    const uint32_t hsb = smem_u32(&hs[0][0][0]);

    // g fragment for this warp's 16 m rows (resident all kernel)
    uint32_t ga0, ga1, ga2, ga3;
    {
        const int mb = m0 + w * 16;
        const float* gp = d_gbuf + (size_t)(b * Nn) * CK;
        ga0 = __float_as_uint(gp[(mb + g) * CK + tg]);
        ga1 = __float_as_uint(gp[(mb + 8 + g) * CK + tg]);
        ga2 = __float_as_uint(gp[(mb + g) * CK + tg + 4]);
        ga3 = __float_as_uint(gp[(mb + 8 + g) * CK + tg + 4]);
    }

    float O[8][4];
#pragma unroll
    for (int cf = 0; cf < 8; cf++)
#pragma unroll
        for (int j = 0; j < 4; j++) O[cf][j] = 0.f;
    float Ls0 = 0.f, Ls1 = 0.f;

    auto issue_tile = [&](int it) {
        const int p  = it & 1;
        const int n0 = it * NT;
        {   // f: 8 rows x 32 chunks of 16B (one per thread)
            int row = tid >> 5, ch = tid & 31;
            CP16(fsb + (uint32_t)(((p * CK + row) * 136 + ch * 4) * 4),
                 d_fbuf + (size_t)(b * CK + row) * Nn + n0 + ch * 4);
        }
#pragma unroll
        for (int t = 0; t < 4; t++) {   // h: 64 pair-rows x 16 chunks
            int e = tid + t * 256;
            int row = e >> 4, ch = e & 15;
            CP16(hsb + (uint32_t)(((p * (NT / 2) + row) * 72 + ch * 4) * 4),
                 d_hpak + (size_t)(b * (Nn / 2) + (n0 >> 1) + row) * Cc + ch * 4);
        }
    };

    issue_tile(0); CP_COMMIT();
    issue_tile(1); CP_COMMIT();

    for (int it = 0; it < NITER; ++it) {
        const int p = it & 1;
        CP_WAIT1();
        __syncthreads();

#pragma unroll
        for (int t = 0; t < NT / 16; t++) {
            // gemm1: two 8-col tf32 tiles covering n in [16t, 16t+16)
            float c0[4] = {0.f, 0.f, 0.f, 0.f};
            float c1[4] = {0.f, 0.f, 0.f, 0.f};
            {
                uint32_t fb0 = __float_as_uint(fs[p][tg][16 * t + g]);
                uint32_t fb1 = __float_as_uint(fs[p][tg + 4][16 * t + g]);
                MMA_TF32(c0, ga0, ga1, ga2, ga3, fb0, fb1);
            }
            {
                uint32_t fb0 = __float_as_uint(fs[p][tg][16 * t + 8 + g]);
                uint32_t fb1 = __float_as_uint(fs[p][tg + 4][16 * t + 8 + g]);
                MMA_TF32(c1, ga0, ga1, ga2, ga3, fb0, fb1);
            }

            // softmax numerators + C->A pack
            float p00 = ex2(c0[0]), p01 = ex2(c0[1]), p02 = ex2(c0[2]), p03 = ex2(c0[3]);
            float p10 = ex2(c1[0]), p11 = ex2(c1[1]), p12 = ex2(c1[2]), p13 = ex2(c1[3]);
            Ls0 += (p00 + p01) + (p10 + p11);
            Ls1 += (p02 + p03) + (p12 + p13);
            uint32_t a0 = packbf(p00, p01);
            uint32_t a1 = packbf(p02, p03);
            uint32_t a2 = packbf(p10, p11);
            uint32_t a3 = packbf(p12, p13);

            // gemm2: O += P(16x16) * h^T, bf16 k16
#pragma unroll
            for (int cf = 0; cf < 8; cf++) {
                uint32_t b0 = hs[p][8 * t + tg][8 * cf + g];
                uint32_t b1 = hs[p][8 * t + tg + 4][8 * cf + g];
                MMA_BF16(O[cf], a0, a1, a2, a3, b0, b1);
            }
        }
        __syncthreads();
        if (it + 2 < NITER) issue_tile(it + 2);
        CP_COMMIT();
    }

    // reduce row sums across the 4-lane quad
    Ls0 += __shfl_xor_sync(0xffffffffu, Ls0, 1);
    Ls0 += __shfl_xor_sync(0xffffffffu, Ls0, 2);
    Ls1 += __shfl_xor_sync(0xffffffffu, Ls1, 1);
    Ls1 += __shfl_xor_sync(0xffffffffu, Ls1, 2);

    // epilogue: out = gamma * O / L + x
    const float ga = gamma[0];
    const float s0 = ga / Ls0;
    const float s1 = ga / Ls1;
    const int r0 = m0 + w * 16 + g;
#pragma unroll
    for (int cf = 0; cf < 8; cf++) {
        const int c0i = cf * 8 + 2 * tg;
        int i00 = (b * Cc + c0i) * Nn + r0;
        int i01 = (b * Cc + c0i + 1) * Nn + r0;
        int i10 = i00 + 8;
        int i11 = i01 + 8;
        out[i00] = fmaf(s0, O[cf][0], x[i00]);
        out[i01] = fmaf(s0, O[cf][1], x[i01]);
        out[i10] = fmaf(s1, O[cf][2], x[i10]);
        out[i11] = fmaf(s1, O[cf][3], x[i11]);
    }
}

// ---------------------------------------------------------------------------
extern "C" void kernel_launch(void* const* d_in, const int* in_sizes, int n_in,
                              void* d_out, int out_size)
{
    const float* x     = (const float*)d_in[0];
    const float* wq    = (const float*)d_in[1];
    const float* wk    = (const float*)d_in[2];
    const float* wv    = (const float*)d_in[3];
    const float* gamma = (const float*)d_in[4];
    float* out = (float*)d_out;
    (void)in_sizes; (void)n_in; (void)out_size;

    proj_kernel<<<dim3(Nn / 128, Bb), 128>>>(x, wq, wk, wv);
    attn_mma_kernel<<<dim3(Nn / MT, Bb), 256>>>(x, gamma, out);
}

// round 5
// speedup vs baseline: 9.4859x; 1.0771x over previous
#include <cuda_runtime.h>
#include <cuda_bf16.h>
#include <cstdint>

// SAGAN self-attention, B=8, C=64, N=4096, Ck=8.
// out = gamma * (h @ softmax_n(f^T g)) + x
// Flash streaming over n, split 2 ways over n (partials combined in kernel 3).
// gemm1 = tf32 m16n8k8 (f pre-permuted to B-frag order), gemm2 = bf16 m16n8k16
// with C->A pack trick and ldmatrix.x4 B-frags. No max-subtraction
// (|s|*log2e <= ~25, exp2 cannot overflow fp32); log2e folded into g.

#define Bb 8
#define Cc 64
#define Nn 4096
#define CK 8
#define MT 128
#define NT 128
#define NSPLIT 2
#define NHALF (Nn / NSPLIT)
#define NITER (NHALF / NT)
#define LOG2E 1.44269504088896340736f

// Scratch (allocation-free rule: __device__ globals)
__device__ float    d_gbuf[Bb * Nn * CK];             // [b][m][k] tf32 * log2e
__device__ float    d_fperm[Bb * (Nn / 16) * 32 * 4]; // B-frag order per 16-n group
__device__ uint16_t d_hbuf[Bb * Cc * Nn];             // bf16 [b][c][n]
__device__ float    d_Opart[NSPLIT * Bb * Nn * Cc];   // [half][b][m][c]
__device__ float    d_Lpart[NSPLIT * Bb * Nn];        // [half][b][m]

// ---------------- helpers ----------------
__device__ __forceinline__ uint32_t smem_u32(const void* p) {
    uint32_t a;
    asm("{ .reg .u64 t; cvta.to.shared.u64 t, %1; cvt.u32.u64 %0, t; }" : "=r"(a) : "l"(p));
    return a;
}
__device__ __forceinline__ float f2tf(float x) {
    uint32_t r;
    asm("cvt.rna.tf32.f32 %0, %1;" : "=r"(r) : "f"(x));
    return __uint_as_float(r);
}
__device__ __forceinline__ float ex2(float x) {
    float r;
    asm("ex2.approx.f32 %0, %1;" : "=f"(r) : "f"(x));
    return r;
}
__device__ __forceinline__ uint32_t packbf(float lo, float hi) {
    uint32_t d;
    asm("cvt.rn.bf16x2.f32 %0, %1, %2;" : "=r"(d) : "f"(hi), "f"(lo));
    return d;
}

#define MMA_TF32(d, a0, a1, a2, a3, b0, b1)                                   \
    asm volatile("mma.sync.aligned.m16n8k8.row.col.f32.tf32.tf32.f32 "        \
                 "{%0,%1,%2,%3}, {%4,%5,%6,%7}, {%8,%9}, {%0,%1,%2,%3};"      \
                 : "+f"((d)[0]), "+f"((d)[1]), "+f"((d)[2]), "+f"((d)[3])     \
                 : "r"(a0), "r"(a1), "r"(a2), "r"(a3), "r"(b0), "r"(b1))

#define MMA_BF16(d, a0, a1, a2, a3, b0, b1)                                   \
    asm volatile("mma.sync.aligned.m16n8k16.row.col.f32.bf16.bf16.f32 "       \
                 "{%0,%1,%2,%3}, {%4,%5,%6,%7}, {%8,%9}, {%0,%1,%2,%3};"      \
                 : "+f"((d)[0]), "+f"((d)[1]), "+f"((d)[2]), "+f"((d)[3])     \
                 : "r"(a0), "r"(a1), "r"(a2), "r"(a3), "r"(b0), "r"(b1))

#define LDMX4(r0, r1, r2, r3, addr)                                           \
    asm volatile("ldmatrix.sync.aligned.m8n8.x4.shared.b16 {%0,%1,%2,%3}, [%4];" \
                 : "=r"(r0), "=r"(r1), "=r"(r2), "=r"(r3) : "r"(addr))

#define CP16(dst, src) \
    asm volatile("cp.async.cg.shared.global [%0], [%1], 16;" :: "r"(dst), "l"(src))
#define CP_COMMIT() asm volatile("cp.async.commit_group;" ::: "memory")
#define CP_WAIT1()  asm volatile("cp.async.wait_group 1;" ::: "memory")

// ---------------------------------------------------------------------------
// Kernel 1: projections, z-split over output rows.
//   z=0: f (B-frag-permuted), g (*log2e), h channels 0..31
//   z=1: h channels 32..63.   h -> bf16 [b][c][n], no transpose needed.
// ---------------------------------------------------------------------------
__global__ __launch_bounds__(128) void proj_kernel(
    const float* __restrict__ x,
    const float* __restrict__ wq,
    const float* __restrict__ wk,
    const float* __restrict__ wv)
{
    __shared__ float w_s[80 * Cc];
    __shared__ float f_stage[8][128];
    const int b   = blockIdx.y;
    const int n0  = blockIdx.x * 128;
    const int z   = blockIdx.z;
    const int tid = threadIdx.x;

    for (int e = tid; e < 80 * Cc; e += 128) {
        int r = e >> 6, c = e & 63;
        float v;
        if (r < 8)       v = wq[r * Cc + c];
        else if (r < 16) v = wk[(r - 8) * Cc + c];
        else             v = wv[(r - 16) * Cc + c];
        w_s[e] = v;
    }
    __syncthreads();

    const int n = n0 + tid;
    float xr[Cc];
#pragma unroll
    for (int c = 0; c < Cc; c++) xr[c] = x[(b * Cc + c) * Nn + n];

    if (z == 0) {
        float ga[8];
#pragma unroll
        for (int r = 0; r < 16; r++) {
            const float4* wr = (const float4*)&w_s[r * Cc];
            float acc = 0.f;
#pragma unroll
            for (int q = 0; q < Cc / 4; q++) {
                float4 w4 = wr[q];
                acc += w4.x * xr[4 * q + 0];
                acc += w4.y * xr[4 * q + 1];
                acc += w4.z * xr[4 * q + 2];
                acc += w4.w * xr[4 * q + 3];
            }
            if (r < 8) f_stage[r][tid] = f2tf(acc);
            else       ga[r - 8] = f2tf(acc * LOG2E);
        }
        float4* gp = (float4*)(d_gbuf + (size_t)(b * Nn + n) * CK);
        gp[0] = make_float4(ga[0], ga[1], ga[2], ga[3]);
        gp[1] = make_float4(ga[4], ga[5], ga[6], ga[7]);
        __syncthreads();
        // permuted f writeout: per 16-n group t, lane l=(g,tg) owns float4
#pragma unroll
        for (int k = 0; k < 2; k++) {
            int e = tid + k * 128;
            int t = e >> 5, l = e & 31, g = l >> 2, tg = l & 3;
            int nl = 16 * t + g;
            float4 v = make_float4(f_stage[tg][nl],     f_stage[tg + 4][nl],
                                   f_stage[tg][nl + 8], f_stage[tg + 4][nl + 8]);
            ((float4*)d_fperm)[(size_t)(b * (Nn / 16) + blockIdx.x * 8 + t) * 32 + l] = v;
        }
    }

    // h channels [32z, 32z+32): value for (c, n=tid) computed locally -> [c][n]
#pragma unroll
    for (int cc = 0; cc < 32; cc++) {
        int r = 16 + z * 32 + cc;
        const float4* wr = (const float4*)&w_s[r * Cc];
        float acc = 0.f;
#pragma unroll
        for (int q = 0; q < Cc / 4; q++) {
            float4 w4 = wr[q];
            acc += w4.x * xr[4 * q + 0];
            acc += w4.y * xr[4 * q + 1];
            acc += w4.z * xr[4 * q + 2];
            acc += w4.w * xr[4 * q + 3];
        }
        __nv_bfloat16 hv = __float2bfloat16(acc);
        d_hbuf[(size_t)(b * Cc + z * 32 + cc) * Nn + n] = *(uint16_t*)&hv;
    }
}

// ---------------------------------------------------------------------------
// Kernel 2: warp-mma flash attention over one n-half.
//   128 threads (4 warps), warp = 32 m (2 m16 frags), MT=128, NT=128.
// ---------------------------------------------------------------------------
__global__ __launch_bounds__(128) void attn_mma_kernel()
{
    __shared__ float4   fsp[2][8][32];       // permuted f, LDS.128 per group
    __shared__ uint16_t hs[2][Cc][136];      // h [c][n] bf16, stride 136 (272B)

    const int tid  = threadIdx.x;
    const int w    = tid >> 5;
    const int lane = tid & 31;
    const int g    = lane >> 2;
    const int tg   = lane & 3;
    const int b    = blockIdx.y;
    const int m0   = blockIdx.x * MT;
    const int half = blockIdx.z;
    const int nbase = half * NHALF;

    const uint32_t fsb = smem_u32(&fsp[0][0][0]);
    const uint32_t hsb = smem_u32(&hs[0][0][0]);

    uint32_t gfr[2][4];
#pragma unroll
    for (int mf = 0; mf < 2; mf++) {
        const int mb = m0 + w * 32 + mf * 16;
        const float* gp = d_gbuf + (size_t)(b * Nn) * CK;
        gfr[mf][0] = __float_as_uint(gp[(mb + g) * CK + tg]);
        gfr[mf][1] = __float_as_uint(gp[(mb + 8 + g) * CK + tg]);
        gfr[mf][2] = __float_as_uint(gp[(mb + g) * CK + tg + 4]);
        gfr[mf][3] = __float_as_uint(gp[(mb + 8 + g) * CK + tg + 4]);
    }

    float O[2][8][4];
#pragma unroll
    for (int mf = 0; mf < 2; mf++)
#pragma unroll
        for (int cf = 0; cf < 8; cf++)
#pragma unroll
            for (int j = 0; j < 4; j++) O[mf][cf][j] = 0.f;
    float Ls[2][2] = {{0.f, 0.f}, {0.f, 0.f}};

    auto issue_tile = [&](int it) {
        const int p  = it & 1;
        const int n0 = nbase + it * NT;
#pragma unroll
        for (int k = 0; k < 2; k++) {   // f: 8 groups x 32 lanes
            int e = tid + k * 128;
            int t = e >> 5, l = e & 31;
            CP16(fsb + (uint32_t)((p * 256 + t * 32 + l) * 16),
                 d_fperm + ((size_t)(b * (Nn / 16) + (n0 >> 4) + t) * 32 + l) * 4);
        }
#pragma unroll
        for (int k = 0; k < 8; k++) {   // h: 64 rows x 16 chunks of 16B
            int e = tid + k * 128;
            int c = e >> 4, ch = e & 15;
            CP16(hsb + (uint32_t)(((p * Cc + c) * 136 + ch * 8) * 2),
                 d_hbuf + (size_t)(b * Cc + c) * Nn + n0 + ch * 8);
        }
    };

    issue_tile(0); CP_COMMIT();
    issue_tile(1); CP_COMMIT();

    // ldmatrix per-thread row/col offsets (within a p2 tile set)
    const uint32_t lm_row = ((lane >> 4) & 1) * 8 + (lane & 7);
    const uint32_t lm_col = ((lane >> 3) & 1) * 8;

    for (int it = 0; it < NITER; ++it) {
        const int p = it & 1;
        CP_WAIT1();
        __syncthreads();

#pragma unroll
        for (int t = 0; t < NT / 16; t++) {
            float4 fv = fsp[p][t][lane];
            uint32_t fb0 = __float_as_uint(fv.x), fb1 = __float_as_uint(fv.y);
            uint32_t fb2 = __float_as_uint(fv.z), fb3 = __float_as_uint(fv.w);

            float c00[4] = {0, 0, 0, 0}, c01[4] = {0, 0, 0, 0};
            float c10[4] = {0, 0, 0, 0}, c11[4] = {0, 0, 0, 0};
            MMA_TF32(c00, gfr[0][0], gfr[0][1], gfr[0][2], gfr[0][3], fb0, fb1);
            MMA_TF32(c01, gfr[0][0], gfr[0][1], gfr[0][2], gfr[0][3], fb2, fb3);
            MMA_TF32(c10, gfr[1][0], gfr[1][1], gfr[1][2], gfr[1][3], fb0, fb1);
            MMA_TF32(c11, gfr[1][0], gfr[1][1], gfr[1][2], gfr[1][3], fb2, fb3);

            uint32_t pa[2][4];
#pragma unroll
            for (int mf = 0; mf < 2; mf++) {
                float* c0 = mf ? c10 : c00;
                float* c1 = mf ? c11 : c01;
                float p00 = ex2(c0[0]), p01 = ex2(c0[1]), p02 = ex2(c0[2]), p03 = ex2(c0[3]);
                float p10 = ex2(c1[0]), p11 = ex2(c1[1]), p12 = ex2(c1[2]), p13 = ex2(c1[3]);
                Ls[mf][0] += (p00 + p01) + (p10 + p11);
                Ls[mf][1] += (p02 + p03) + (p12 + p13);
                pa[mf][0] = packbf(p00, p01);
                pa[mf][1] = packbf(p02, p03);
                pa[mf][2] = packbf(p10, p11);
                pa[mf][3] = packbf(p12, p13);
            }

#pragma unroll
            for (int p2 = 0; p2 < 4; p2++) {
                uint32_t r0, r1, r2, r3;
                uint32_t addr = hsb + ((p * Cc + 16 * p2 + lm_row) * 136 + 16 * t + lm_col) * 2;
                LDMX4(r0, r1, r2, r3, addr);
                const int cf = 2 * p2;
                MMA_BF16(O[0][cf],     pa[0][0], pa[0][1], pa[0][2], pa[0][3], r0, r1);
                MMA_BF16(O[1][cf],     pa[1][0], pa[1][1], pa[1][2], pa[1][3], r0, r1);
                MMA_BF16(O[0][cf + 1], pa[0][0], pa[0][1], pa[0][2], pa[0][3], r2, r3);
                MMA_BF16(O[1][cf + 1], pa[1][0], pa[1][1], pa[1][2], pa[1][3], r2, r3);
            }
        }
        __syncthreads();
        if (it + 2 < NITER) issue_tile(it + 2);
        CP_COMMIT();
    }

    // quad-reduce row sums
#pragma unroll
    for (int mf = 0; mf < 2; mf++)
#pragma unroll
        for (int hh = 0; hh < 2; hh++) {
            float v = Ls[mf][hh];
            v += __shfl_xor_sync(0xffffffffu, v, 1);
            v += __shfl_xor_sync(0xffffffffu, v, 2);
            Ls[mf][hh] = v;
        }

    // write partials: O numerators [half][b][m][c], L [half][b][m]
    const size_t base = (size_t)(half * Bb + b) * Nn;
#pragma unroll
    for (int mf = 0; mf < 2; mf++) {
        const int r = m0 + w * 32 + mf * 16 + g;
#pragma unroll
        for (int cf = 0; cf < 8; cf++) {
            const int c = cf * 8 + 2 * tg;
            *(float2*)&d_Opart[(base + r) * Cc + c]     = make_float2(O[mf][cf][0], O[mf][cf][1]);
            *(float2*)&d_Opart[(base + r + 8) * Cc + c] = make_float2(O[mf][cf][2], O[mf][cf][3]);
        }
        if (tg == 0) {
            d_Lpart[base + r]     = Ls[mf][0];
            d_Lpart[base + r + 8] = Ls[mf][1];
        }
    }
}

// ---------------------------------------------------------------------------
// Kernel 3: combine halves + residual.  out[b][c][m] = ga*(O0+O1)/(L0+L1) + x
// Block: 64 m x 64 c tile, smem transpose, fully coalesced.
// ---------------------------------------------------------------------------
__global__ __launch_bounds__(256) void combine_kernel(
    const float* __restrict__ x,
    const float* __restrict__ gamma,
    float* __restrict__ out)
{
    __shared__ float sL[64];
    __shared__ float s[64][65];
    const int b   = blockIdx.y;
    const int m0  = blockIdx.x * 64;
    const int tid = threadIdx.x;
    const float ga = gamma[0];

    if (tid < 64) {
        float L = d_Lpart[(size_t)(0 * Bb + b) * Nn + m0 + tid]
                + d_Lpart[(size_t)(1 * Bb + b) * Nn + m0 + tid];
        sL[tid] = ga / L;
    }
    __syncthreads();

#pragma unroll
    for (int k = 0; k < 4; k++) {
        int e = tid + k * 256;
        int ml = e >> 4, cq = e & 15;
        const float4 a  = *(const float4*)&d_Opart[((size_t)(0 * Bb + b) * Nn + m0 + ml) * Cc + cq * 4];
        const float4 b2 = *(const float4*)&d_Opart[((size_t)(1 * Bb + b) * Nn + m0 + ml) * Cc + cq * 4];
        const float inv = sL[ml];
        s[cq * 4 + 0][ml] = (a.x + b2.x) * inv;
        s[cq * 4 + 1][ml] = (a.y + b2.y) * inv;
        s[cq * 4 + 2][ml] = (a.z + b2.z) * inv;
        s[cq * 4 + 3][ml] = (a.w + b2.w) * inv;
    }
    __syncthreads();

#pragma unroll
    for (int k = 0; k < 4; k++) {
        int e = tid + k * 256;
        int c = e >> 4, mq = e & 15;
        int gi = (b * Cc + c) * Nn + m0 + mq * 4;
        float4 xv = *(const float4*)&x[gi];
        float4 o;
        o.x = s[c][mq * 4 + 0] + xv.x;
        o.y = s[c][mq * 4 + 1] + xv.y;
        o.z = s[c][mq * 4 + 2] + xv.z;
        o.w = s[c][mq * 4 + 3] + xv.w;
        *(float4*)&out[gi] = o;
    }
}

// ---------------------------------------------------------------------------
extern "C" void kernel_launch(void* const* d_in, const int* in_sizes, int n_in,
                              void* d_out, int out_size)
{
    const float* x     = (const float*)d_in[0];
    const float* wq    = (const float*)d_in[1];
    const float* wk    = (const float*)d_in[2];
    const float* wv    = (const float*)d_in[3];
    const float* gamma = (const float*)d_in[4];
    float* out = (float*)d_out;
    (void)in_sizes; (void)n_in; (void)out_size;

    proj_kernel<<<dim3(Nn / 128, Bb, 2), 128>>>(x, wq, wk, wv);
    attn_mma_kernel<<<dim3(Nn / MT, Bb, NSPLIT), 128>>>();
    combine_kernel<<<dim3(Nn / 64, Bb), 256>>>(x, gamma, out);
}

// round 7
// speedup vs baseline: 10.1048x; 1.0652x over previous
#include <cuda_runtime.h>
#include <cuda_bf16.h>
#include <cstdint>

// SAGAN self-attention, B=8, C=64, N=4096, Ck=8.
// out = gamma * (h @ softmax_n(f^T g)) + x
// Flash streaming over n, split 4 ways over n (partials combined in kernel 3).
// gemm1 = tf32 m16n8k8 (f pre-permuted to B-frag order), gemm2 = bf16 m16n8k16
// with C->A pack trick and ldmatrix.x4 B-frags. No max-subtraction
// (|s|*log2e <= ~25, exp2 cannot overflow fp32); log2e folded into g.

#define Bb 8
#define Cc 64
#define Nn 4096
#define CK 8
#define MT 128
#define NT 64
#define NSPLIT 4
#define NHALF (Nn / NSPLIT)
#define NITER (NHALF / NT)
#define LOG2E 1.44269504088896340736f

// Scratch (allocation-free rule: __device__ globals)
__device__ float    d_gbuf[Bb * Nn * CK];             // [b][m][k] tf32 * log2e
__device__ float    d_fperm[Bb * (Nn / 16) * 32 * 4]; // B-frag order per 16-n group
__device__ uint16_t d_hbuf[Bb * Cc * Nn];             // bf16 [b][c][n]
__device__ float    d_Opart[NSPLIT * Bb * Nn * Cc];   // [part][b][m][c]
__device__ float    d_Lpart[NSPLIT * Bb * Nn];        // [part][b][m]

// ---------------- helpers ----------------
__device__ __forceinline__ uint32_t smem_u32(const void* p) {
    uint32_t a;
    asm("{ .reg .u64 t; cvta.to.shared.u64 t, %1; cvt.u32.u64 %0, t; }" : "=r"(a) : "l"(p));
    return a;
}
__device__ __forceinline__ float f2tf(float x) {
    uint32_t r;
    asm("cvt.rna.tf32.f32 %0, %1;" : "=r"(r) : "f"(x));
    return __uint_as_float(r);
}
__device__ __forceinline__ float ex2(float x) {
    float r;
    asm("ex2.approx.f32 %0, %1;" : "=f"(r) : "f"(x));
    return r;
}
__device__ __forceinline__ uint32_t packbf(float lo, float hi) {
    uint32_t d;
    asm("cvt.rn.bf16x2.f32 %0, %1, %2;" : "=r"(d) : "f"(hi), "f"(lo));
    return d;
}

#define MMA_TF32(d, a0, a1, a2, a3, b0, b1)                                   \
    asm volatile("mma.sync.aligned.m16n8k8.row.col.f32.tf32.tf32.f32 "        \
                 "{%0,%1,%2,%3}, {%4,%5,%6,%7}, {%8,%9}, {%0,%1,%2,%3};"      \
                 : "+f"((d)[0]), "+f"((d)[1]), "+f"((d)[2]), "+f"((d)[3])     \
                 : "r"(a0), "r"(a1), "r"(a2), "r"(a3), "r"(b0), "r"(b1))

#define MMA_BF16(d, a0, a1, a2, a3, b0, b1)                                   \
    asm volatile("mma.sync.aligned.m16n8k16.row.col.f32.bf16.bf16.f32 "       \
                 "{%0,%1,%2,%3}, {%4,%5,%6,%7}, {%8,%9}, {%0,%1,%2,%3};"      \
                 : "+f"((d)[0]), "+f"((d)[1]), "+f"((d)[2]), "+f"((d)[3])     \
                 : "r"(a0), "r"(a1), "r"(a2), "r"(a3), "r"(b0), "r"(b1))

#define LDMX4(r0, r1, r2, r3, addr)                                           \
    asm volatile("ldmatrix.sync.aligned.m8n8.x4.shared.b16 {%0,%1,%2,%3}, [%4];" \
                 : "=r"(r0), "=r"(r1), "=r"(r2), "=r"(r3) : "r"(addr))

#define CP16(dst, src) \
    asm volatile("cp.async.cg.shared.global [%0], [%1], 16;" :: "r"(dst), "l"(src))
#define CP_COMMIT() asm volatile("cp.async.commit_group;" ::: "memory")
#define CP_WAIT1()  asm volatile("cp.async.wait_group 1;" ::: "memory")

// ---------------------------------------------------------------------------
// Kernel 1: projections, split-K x2.
//   128 threads = 64 pixels x 2 K-halves. Thread computes 80 partial dots over
//   its 32 channels; pair-combine via shfl_xor(1). w in smem [r][kh][36].
//   f B-frag-permuted, g *log2e tf32, h bf16 [b][c][n].
// ---------------------------------------------------------------------------
__global__ __launch_bounds__(128) void proj_kernel(
    const float* __restrict__ x,
    const float* __restrict__ wq,
    const float* __restrict__ wk,
    const float* __restrict__ wv)
{
    __shared__ float w_s[80 * 2 * 36];
    __shared__ float f_stage[8][64];
    const int b   = blockIdx.y;
    const int n0  = blockIdx.x * 64;
    const int tid = threadIdx.x;
    const int p   = tid >> 1;       // pixel 0..63
    const int kh  = tid & 1;        // K half
    const int n   = n0 + p;

    for (int e = tid; e < 80 * 64; e += 128) {
        int r = e >> 6, cc = e & 63;
        float v;
        if (r < 8)       v = wq[r * Cc + cc];
        else if (r < 16) v = wk[(r - 8) * Cc + cc];
        else             v = wv[(r - 16) * Cc + cc];
        w_s[(r * 2 + (cc >> 5)) * 36 + (cc & 31)] = v;
    }
    __syncthreads();

    float xr[32];
#pragma unroll
    for (int c = 0; c < 32; c++) xr[c] = x[(b * Cc + kh * 32 + c) * Nn + n];

    for (int rg = 0; rg < 10; rg++) {
        float acc[8];
#pragma unroll
        for (int j = 0; j < 8; j++) {
            const float4* wr = (const float4*)&w_s[((rg * 8 + j) * 2 + kh) * 36];
            float a = 0.f;
#pragma unroll
            for (int q = 0; q < 8; q++) {
                float4 w4 = wr[q];
                a += w4.x * xr[4 * q + 0];
                a += w4.y * xr[4 * q + 1];
                a += w4.z * xr[4 * q + 2];
                a += w4.w * xr[4 * q + 3];
            }
            acc[j] = a;
        }
#pragma unroll
        for (int j = 0; j < 8; j++)
            acc[j] += __shfl_xor_sync(0xffffffffu, acc[j], 1);

        if (rg == 0) {
            if (kh == 0)
#pragma unroll
                for (int j = 0; j < 8; j++) f_stage[j][p] = f2tf(acc[j]);
        } else if (rg == 1) {
            if (kh == 0) {
                float4* gp = (float4*)(d_gbuf + (size_t)(b * Nn + n) * CK);
                gp[0] = make_float4(f2tf(acc[0] * LOG2E), f2tf(acc[1] * LOG2E),
                                    f2tf(acc[2] * LOG2E), f2tf(acc[3] * LOG2E));
                gp[1] = make_float4(f2tf(acc[4] * LOG2E), f2tf(acc[5] * LOG2E),
                                    f2tf(acc[6] * LOG2E), f2tf(acc[7] * LOG2E));
            }
        } else {
            // h output channel = weight row - 16 = (rg-2)*8 + j   (FIX: no +16)
            const int c0 = (rg - 2) * 8;
#pragma unroll
            for (int j = 0; j < 8; j++) {
                if ((j & 1) == kh) {
                    __nv_bfloat16 hv = __float2bfloat16(acc[j]);
                    d_hbuf[(size_t)(b * Cc + c0 + j) * Nn + n] = *(uint16_t*)&hv;
                }
            }
        }
    }
    __syncthreads();

    // permuted f writeout: 4 groups of 16 pixels, 32 lanes each
    {
        int t = tid >> 5, l = tid & 31, g = l >> 2, tg = l & 3;
        int nl = 16 * t + g;
        float4 v = make_float4(f_stage[tg][nl],     f_stage[tg + 4][nl],
                               f_stage[tg][nl + 8], f_stage[tg + 4][nl + 8]);
        ((float4*)d_fperm)[(size_t)(b * (Nn / 16) + blockIdx.x * 4 + t) * 32 + l] = v;
    }
}

// ---------------------------------------------------------------------------
// Kernel 2: warp-mma flash attention over one n-quarter.
//   128 threads (4 warps), warp = 32 m (2 m16 frags), MT=128, NT=64.
// ---------------------------------------------------------------------------
__global__ __launch_bounds__(128) void attn_mma_kernel()
{
    __shared__ float4   fsp[2][4][32];       // permuted f
    __shared__ uint16_t hs[2][Cc][72];       // h [c][n] bf16, stride 72 (144B)

    const int tid  = threadIdx.x;
    const int w    = tid >> 5;
    const int lane = tid & 31;
    const int g    = lane >> 2;
    const int tg   = lane & 3;
    const int b    = blockIdx.y;
    const int m0   = blockIdx.x * MT;
    const int part = blockIdx.z;
    const int nbase = part * NHALF;

    const uint32_t fsb = smem_u32(&fsp[0][0][0]);
    const uint32_t hsb = smem_u32(&hs[0][0][0]);

    uint32_t gfr[2][4];
#pragma unroll
    for (int mf = 0; mf < 2; mf++) {
        const int mb = m0 + w * 32 + mf * 16;
        const float* gp = d_gbuf + (size_t)(b * Nn) * CK;
        gfr[mf][0] = __float_as_uint(gp[(mb + g) * CK + tg]);
        gfr[mf][1] = __float_as_uint(gp[(mb + 8 + g) * CK + tg]);
        gfr[mf][2] = __float_as_uint(gp[(mb + g) * CK + tg + 4]);
        gfr[mf][3] = __float_as_uint(gp[(mb + 8 + g) * CK + tg + 4]);
    }

    float O[2][8][4];
#pragma unroll
    for (int mf = 0; mf < 2; mf++)
#pragma unroll
        for (int cf = 0; cf < 8; cf++)
#pragma unroll
            for (int j = 0; j < 4; j++) O[mf][cf][j] = 0.f;
    float Ls[2][2] = {{0.f, 0.f}, {0.f, 0.f}};

    auto issue_tile = [&](int it) {
        const int p  = it & 1;
        const int n0 = nbase + it * NT;
        {   // f: 4 groups x 32 lanes = 128 cp16
            int t = tid >> 5, l = tid & 31;
            CP16(fsb + (uint32_t)((p * 128 + t * 32 + l) * 16),
                 d_fperm + ((size_t)(b * (Nn / 16) + (n0 >> 4) + t) * 32 + l) * 4);
        }
#pragma unroll
        for (int k = 0; k < 4; k++) {   // h: 64 rows x 8 chunks of 16B
            int e = tid + k * 128;
            int c = e >> 3, ch = e & 7;
            CP16(hsb + (uint32_t)(((p * Cc + c) * 72 + ch * 8) * 2),
                 d_hbuf + (size_t)(b * Cc + c) * Nn + n0 + ch * 8);
        }
    };

    issue_tile(0); CP_COMMIT();
    issue_tile(1); CP_COMMIT();

    const uint32_t lm_row = ((lane >> 4) & 1) * 8 + (lane & 7);
    const uint32_t lm_col = ((lane >> 3) & 1) * 8;

    for (int it = 0; it < NITER; ++it) {
        const int p = it & 1;
        CP_WAIT1();
        __syncthreads();

#pragma unroll
        for (int t = 0; t < NT / 16; t++) {
            float4 fv = fsp[p][t][lane];
            uint32_t fb0 = __float_as_uint(fv.x), fb1 = __float_as_uint(fv.y);
            uint32_t fb2 = __float_as_uint(fv.z), fb3 = __float_as_uint(fv.w);

            float c00[4] = {0, 0, 0, 0}, c01[4] = {0, 0, 0, 0};
            float c10[4] = {0, 0, 0, 0}, c11[4] = {0, 0, 0, 0};
            MMA_TF32(c00, gfr[0][0], gfr[0][1], gfr[0][2], gfr[0][3], fb0, fb1);
            MMA_TF32(c01, gfr[0][0], gfr[0][1], gfr[0][2], gfr[0][3], fb2, fb3);
            MMA_TF32(c10, gfr[1][0], gfr[1][1], gfr[1][2], gfr[1][3], fb0, fb1);
            MMA_TF32(c11, gfr[1][0], gfr[1][1], gfr[1][2], gfr[1][3], fb2, fb3);

            uint32_t pa[2][4];
#pragma unroll
            for (int mf = 0; mf < 2; mf++) {
                float* c0 = mf ? c10 : c00;
                float* c1 = mf ? c11 : c01;
                float p00 = ex2(c0[0]), p01 = ex2(c0[1]), p02 = ex2(c0[2]), p03 = ex2(c0[3]);
                float p10 = ex2(c1[0]), p11 = ex2(c1[1]), p12 = ex2(c1[2]), p13 = ex2(c1[3]);
                Ls[mf][0] += (p00 + p01) + (p10 + p11);
                Ls[mf][1] += (p02 + p03) + (p12 + p13);
                pa[mf][0] = packbf(p00, p01);
                pa[mf][1] = packbf(p02, p03);
                pa[mf][2] = packbf(p10, p11);
                pa[mf][3] = packbf(p12, p13);
            }

#pragma unroll
            for (int p2 = 0; p2 < 4; p2++) {
                uint32_t r0, r1, r2, r3;
                uint32_t addr = hsb + ((p * Cc + 16 * p2 + lm_row) * 72 + 16 * t + lm_col) * 2;
                LDMX4(r0, r1, r2, r3, addr);
                const int cf = 2 * p2;
                MMA_BF16(O[0][cf],     pa[0][0], pa[0][1], pa[0][2], pa[0][3], r0, r1);
                MMA_BF16(O[1][cf],     pa[1][0], pa[1][1], pa[1][2], pa[1][3], r0, r1);
                MMA_BF16(O[0][cf + 1], pa[0][0], pa[0][1], pa[0][2], pa[0][3], r2, r3);
                MMA_BF16(O[1][cf + 1], pa[1][0], pa[1][1], pa[1][2], pa[1][3], r2, r3);
            }
        }
        __syncthreads();
        if (it + 2 < NITER) issue_tile(it + 2);
        CP_COMMIT();
    }

    // quad-reduce row sums
#pragma unroll
    for (int mf = 0; mf < 2; mf++)
#pragma unroll
        for (int hh = 0; hh < 2; hh++) {
            float v = Ls[mf][hh];
            v += __shfl_xor_sync(0xffffffffu, v, 1);
            v += __shfl_xor_sync(0xffffffffu, v, 2);
            Ls[mf][hh] = v;
        }

    // write partials
    const size_t base = (size_t)(part * Bb + b) * Nn;
#pragma unroll
    for (int mf = 0; mf < 2; mf++) {
        const int r = m0 + w * 32 + mf * 16 + g;
#pragma unroll
        for (int cf = 0; cf < 8; cf++) {
            const int c = cf * 8 + 2 * tg;
            *(float2*)&d_Opart[(base + r) * Cc + c]     = make_float2(O[mf][cf][0], O[mf][cf][1]);
            *(float2*)&d_Opart[(base + r + 8) * Cc + c] = make_float2(O[mf][cf][2], O[mf][cf][3]);
        }
        if (tg == 0) {
            d_Lpart[base + r]     = Ls[mf][0];
            d_Lpart[base + r + 8] = Ls[mf][1];
        }
    }
}

// ---------------------------------------------------------------------------
// Kernel 3: combine 4 parts + residual.  out[b][c][m] = ga*sum(O)/sum(L) + x
// ---------------------------------------------------------------------------
__global__ __launch_bounds__(256) void combine_kernel(
    const float* __restrict__ x,
    const float* __restrict__ gamma,
    float* __restrict__ out)
{
    __shared__ float sL[64];
    __shared__ float s[64][65];
    const int b   = blockIdx.y;
    const int m0  = blockIdx.x * 64;
    const int tid = threadIdx.x;
    const float ga = gamma[0];

    if (tid < 64) {
        float L = 0.f;
#pragma unroll
        for (int hh = 0; hh < NSPLIT; hh++)
            L += d_Lpart[(size_t)(hh * Bb + b) * Nn + m0 + tid];
        sL[tid] = ga / L;
    }
    __syncthreads();

#pragma unroll
    for (int k = 0; k < 4; k++) {
        int e = tid + k * 256;
        int ml = e >> 4, cq = e & 15;
        float4 a = make_float4(0.f, 0.f, 0.f, 0.f);
#pragma unroll
        for (int hh = 0; hh < NSPLIT; hh++) {
            const float4 v = *(const float4*)&d_Opart[((size_t)(hh * Bb + b) * Nn + m0 + ml) * Cc + cq * 4];
            a.x += v.x; a.y += v.y; a.z += v.z; a.w += v.w;
        }
        const float inv = sL[ml];
        s[cq * 4 + 0][ml] = a.x * inv;
        s[cq * 4 + 1][ml] = a.y * inv;
        s[cq * 4 + 2][ml] = a.z * inv;
        s[cq * 4 + 3][ml] = a.w * inv;
    }
    __syncthreads();

#pragma unroll
    for (int k = 0; k < 4; k++) {
        int e = tid + k * 256;
        int c = e >> 4, mq = e & 15;
        int gi = (b * Cc + c) * Nn + m0 + mq * 4;
        float4 xv = *(const float4*)&x[gi];
        float4 o;
        o.x = s[c][mq * 4 + 0] + xv.x;
        o.y = s[c][mq * 4 + 1] + xv.y;
        o.z = s[c][mq * 4 + 2] + xv.z;
        o.w = s[c][mq * 4 + 3] + xv.w;
        *(float4*)&out[gi] = o;
    }
}

// ---------------------------------------------------------------------------
extern "C" void kernel_launch(void* const* d_in, const int* in_sizes, int n_in,
                              void* d_out, int out_size)
{
    const float* x     = (const float*)d_in[0];
    const float* wq    = (const float*)d_in[1];
    const float* wk    = (const float*)d_in[2];
    const float* wv    = (const float*)d_in[3];
    const float* gamma = (const float*)d_in[4];
    float* out = (float*)d_out;
    (void)in_sizes; (void)n_in; (void)out_size;

    proj_kernel<<<dim3(Nn / 64, Bb), 128>>>(x, wq, wk, wv);
    attn_mma_kernel<<<dim3(Nn / MT, Bb, NSPLIT), 128>>>();
    combine_kernel<<<dim3(Nn / 64, Bb), 256>>>(x, gamma, out);
}